// round 17
// baseline (speedup 1.0000x reference)
#include <cuda_runtime.h>

#define BB 8
#define LL 2048
#define DD 2048
#define NN 16
#define ROWS (BB*LL)
#define CS 32
#define CPB (LL/CS)
#define NCHUNK (ROWS/CS)

__device__ float g_delta[ROWS];
__device__ float g_Bt[ROWS*NN];
__device__ float g_Ct[ROWS*NN];
__device__ float g_Dt[ROWS];
__device__ float g_cP[NCHUNK*NN*NN];
__device__ float g_cq[NCHUNK*NN];
__device__ float g_cS[NCHUNK*NN];
__device__ float g_V[ROWS*NN];      // v_t = P_t^T Ct_t
__device__ float g_C[ROWS];         // c_t = Ct_t . q_t + Dt_t
__device__ __align__(16) float2 g_Wp[40*2048];  // hi/lo tf32 split of [Wb;Wc;Wd;dp]

__device__ __forceinline__ unsigned s2u(const void* p) {
    unsigned a;
    asm("{ .reg .u64 t; cvta.to.shared.u64 t, %1; cvt.u32.u64 %0, t; }" : "=r"(a) : "l"(p));
    return a;
}
#define CP16(d, s) asm volatile("cp.async.ca.shared.global [%0], [%1], 16;\n" :: "r"(d), "l"(s))
#define CPCOMMIT() asm volatile("cp.async.commit_group;\n")
#define CPWAIT1()  asm volatile("cp.async.wait_group 1;\n")

__device__ __forceinline__ unsigned tf32b(float x) {
    unsigned y;
    asm("cvt.rna.tf32.f32 %0, %1;" : "=r"(y) : "f"(x));
    return y;
}
__device__ __forceinline__ float tf32f(float x) {
    return __uint_as_float(tf32b(x));
}
__device__ __forceinline__ void mma8(float c[4], unsigned a0, unsigned a1,
                                     unsigned a2, unsigned a3,
                                     unsigned b0, unsigned b1) {
    asm volatile(
        "mma.sync.aligned.m16n8k8.row.col.f32.tf32.tf32.f32 "
        "{%0,%1,%2,%3}, {%4,%5,%6,%7}, {%8,%9}, {%0,%1,%2,%3};"
        : "+f"(c[0]), "+f"(c[1]), "+f"(c[2]), "+f"(c[3])
        : "r"(a0), "r"(a1), "r"(a2), "r"(a3), "r"(b0), "r"(b1));
}

// ---------------- K0: split W into tf32 hi/lo pairs ----------------
__global__ __launch_bounds__(256) void k0_wsplit(
    const float* __restrict__ Wb, const float* __restrict__ Wc,
    const float* __restrict__ Wd, const float* __restrict__ dp)
{
    int idx = blockIdx.x * 256 + threadIdx.x;
    int r = idx >> 11, c = idx & 2047;
    float v = 0.f;
    if (r < 16)       v = Wb[r * DD + c];
    else if (r < 32)  v = Wc[(r - 16) * DD + c];
    else if (r == 32) v = Wd[c];
    else if (r == 33) v = dp[c];
    float h = tf32f(v);
    g_Wp[idx] = make_float2(h, tf32f(v - h));
}

// ---------------- K1: tf32x3 tensor-core projections, cp.async staged ------
__global__ __launch_bounds__(128) void k1_proj(
    const float* __restrict__ u,
    const float* __restrict__ bb, const float* __restrict__ bc,
    const float* __restrict__ bd)
{
    __shared__ float  sUraw[2][64 * 36];
    __shared__ float2 sW[2][40 * 36];
    const int tid = threadIdx.x;
    const int w = tid >> 5, lane = tid & 31;
    const int g = lane >> 2, t = lane & 3;
    const int row0 = blockIdx.x * 64;
    const int wrow = w * 16;

    const unsigned su0 = s2u(&sUraw[0][0]);
    const unsigned sw0 = s2u(&sW[0][0]);

    auto issueK = [&](int bi, int kc) {
        unsigned du = su0 + bi * (64 * 36) * 4;
#pragma unroll
        for (int j = 0; j < 4; j++) {
            int idx = tid + 128 * j;
            int r = idx >> 3, c4 = idx & 7;
            CP16(du + (r * 36 + c4 * 4) * 4,
                 u + (size_t)(row0 + r) * DD + kc * 32 + c4 * 4);
        }
        unsigned dw = sw0 + bi * (40 * 36) * 8;
#pragma unroll
        for (int j = 0; j < 5; j++) {
            int idx = tid + 128 * j;
            int r = idx >> 4, q = idx & 15;
            CP16(dw + (r * 36 + q * 2) * 8, &g_Wp[r * 2048 + kc * 32 + q * 2]);
        }
    };

    float acc[5][4];
#pragma unroll
    for (int n = 0; n < 5; n++)
#pragma unroll
        for (int m = 0; m < 4; m++) acc[n][m] = 0.f;

    issueK(0, 0); CPCOMMIT();
    issueK(1, 1); CPCOMMIT();

    for (int kc = 0; kc < 64; kc++) {
        CPWAIT1();
        __syncthreads();
        const int bi = kc & 1;
        const float*  Ub = &sUraw[bi][0];
        const float2* Wb2 = &sW[bi][0];
#pragma unroll
        for (int ks = 0; ks < 4; ks++) {
            int k = ks * 8;
            float a0 = Ub[(wrow + g) * 36 + k + t];
            float a1 = Ub[(wrow + g + 8) * 36 + k + t];
            float a2 = Ub[(wrow + g) * 36 + k + t + 4];
            float a3 = Ub[(wrow + g + 8) * 36 + k + t + 4];
            unsigned ah0 = tf32b(a0), ah1 = tf32b(a1), ah2 = tf32b(a2), ah3 = tf32b(a3);
            unsigned al0 = tf32b(a0 - __uint_as_float(ah0));
            unsigned al1 = tf32b(a1 - __uint_as_float(ah1));
            unsigned al2 = tf32b(a2 - __uint_as_float(ah2));
            unsigned al3 = tf32b(a3 - __uint_as_float(ah3));
#pragma unroll
            for (int nt = 0; nt < 5; nt++) {
                float2 b0p = Wb2[(nt * 8 + g) * 36 + k + t];
                float2 b1p = Wb2[(nt * 8 + g) * 36 + k + t + 4];
                unsigned bh0 = __float_as_uint(b0p.x), bl0 = __float_as_uint(b0p.y);
                unsigned bh1 = __float_as_uint(b1p.x), bl1 = __float_as_uint(b1p.y);
                mma8(acc[nt], ah0, ah1, ah2, ah3, bh0, bh1);
                mma8(acc[nt], ah0, ah1, ah2, ah3, bl0, bl1);
                mma8(acc[nt], al0, al1, al2, al3, bh0, bh1);
            }
        }
        __syncthreads();
        if (kc + 2 < 64) issueK(bi, kc + 2);
        CPCOMMIT();
    }
    const int rlo = row0 + wrow + g, rhi = rlo + 8;
#pragma unroll
    for (int nt = 0; nt < 5; nt++) {
#pragma unroll
        for (int m = 0; m < 4; m++) {
            int row = (m & 2) ? rhi : rlo;
            int col = nt * 8 + 2 * t + (m & 1);
            float v = acc[nt][m];
            if (col < 16)       g_Bt[row * NN + col] = v + bb[col];
            else if (col < 32)  g_Ct[row * NN + col - 16] = v + bc[col - 16];
            else if (col == 32) g_Dt[row] = v + bd[0];
            else if (col == 33) g_delta[row] = 1.f / (1.f + __expf(-v));
        }
    }
}

// ---------------- fused expm + chunk scan ----------------
#define C3f 1.6666667e-1f
#define C4f 4.1666668e-2f
#define C5f 8.3333333e-3f
#define C6f 1.3888889e-3f
#define C7f 1.9841270e-4f
#define C8f 2.4801587e-5f
#define C9f 2.7557319e-6f

__device__ __forceinline__ void mm16(const float* __restrict__ A,
                                     const float* __restrict__ Bm,
                                     int i0, int j0, float c[4][4])
{
#pragma unroll
    for (int r = 0; r < 4; r++)
#pragma unroll
        for (int q = 0; q < 4; q++) c[r][q] = 0.f;
#pragma unroll
    for (int k = 0; k < 16; k++) {
        float b0 = Bm[k * 17 + j0 + 0];
        float b1 = Bm[k * 17 + j0 + 1];
        float b2 = Bm[k * 17 + j0 + 2];
        float b3 = Bm[k * 17 + j0 + 3];
#pragma unroll
        for (int r = 0; r < 4; r++) {
            float a = A[(i0 + r) * 17 + k];
            c[r][0] = fmaf(a, b0, c[r][0]);
            c[r][1] = fmaf(a, b1, c[r][1]);
            c[r][2] = fmaf(a, b2, c[r][2]);
            c[r][3] = fmaf(a, b3, c[r][3]);
        }
    }
}

// smem layout (floats)
#define F_AD   0                     // 32 * 272 = 8704  (M slot, becomes Ad)
#define F_SCR  8704                  // 8 * 816 = 6528   (M2, M3, T per group)
#define F_P0   15232                 // 272
#define F_P1   15504                 // 272
#define F_QB   15776                 // 32
#define F_SBT  15808                 // 512
#define F_SCT  16320                 // 512
#define F_SDT  16832                 // 32
#define F_TOT  16864
#define FUSED_SMEM (F_TOT * 4)

__device__ __forceinline__ void expm_inplace(float* M, float* scr, int q)
{
    const int i0 = (q >> 2) * 4, j0 = (q & 3) * 4;
    float* M2 = scr;
    float* M3 = scr + 272;
    float* T  = scr + 544;
    float c[4][4];

    mm16(M, M, i0, j0, c);                       // M2 = M*M
#pragma unroll
    for (int r = 0; r < 4; r++)
#pragma unroll
        for (int cc = 0; cc < 4; cc++) M2[(i0 + r) * 17 + j0 + cc] = c[r][cc];
    __syncwarp();
    mm16(M2, M, i0, j0, c);                      // M3 = M2*M
#pragma unroll
    for (int r = 0; r < 4; r++)
#pragma unroll
        for (int cc = 0; cc < 4; cc++) M3[(i0 + r) * 17 + j0 + cc] = c[r][cc];
    __syncwarp();
#pragma unroll
    for (int r = 0; r < 4; r++)                  // T = b2
#pragma unroll
        for (int cc = 0; cc < 4; cc++) {
            int idx = (i0 + r) * 17 + j0 + cc;
            float val = C7f * M[idx] + C8f * M2[idx] + C9f * M3[idx];
            if (i0 + r == j0 + cc) val += C6f;
            T[idx] = val;
        }
    __syncwarp();
    mm16(M3, T, i0, j0, c);                      // T <- M3*T + b1 (in place)
    __syncwarp();
#pragma unroll
    for (int r = 0; r < 4; r++)
#pragma unroll
        for (int cc = 0; cc < 4; cc++) {
            int idx = (i0 + r) * 17 + j0 + cc;
            float val = c[r][cc] + C4f * M[idx] + C5f * M2[idx];
            if (i0 + r == j0 + cc) val += C3f;
            T[idx] = val;
        }
    __syncwarp();
    mm16(M3, T, i0, j0, c);                      // T <- M3*T + b0 (in place)
    __syncwarp();
#pragma unroll
    for (int r = 0; r < 4; r++)
#pragma unroll
        for (int cc = 0; cc < 4; cc++) {
            int idx = (i0 + r) * 17 + j0 + cc;
            float val = c[r][cc] + M[idx] + 0.5f * M2[idx];
            if (i0 + r == j0 + cc) val += 1.f;
            T[idx] = val;
        }
    __syncwarp();
    mm16(T, T, i0, j0, c);                       // Ad = T*T -> M slot
#pragma unroll
    for (int r = 0; r < 4; r++)
#pragma unroll
        for (int cc = 0; cc < 4; cc++) M[(i0 + r) * 17 + j0 + cc] = c[r][cc];
}

__global__ __launch_bounds__(512) void k_fused(const float* __restrict__ Ag)
{
    extern __shared__ float sm[];
    const int tid = threadIdx.x;
    const int chunk = blockIdx.x;
    const size_t row0 = (size_t)chunk * CS;

    // stage A (scaled by delta/2) into the 32 M slots, coalesced float4
    for (int j = tid; j < 2048; j += 512) {
        int m = j >> 6, f = j & 63, r = f >> 2, c4 = f & 3;
        int t = (int)((row0 + m) & (LL - 1));
        float4 v = *reinterpret_cast<const float4*>(Ag + (size_t)t * 256 + r * 16 + c4 * 4);
        float sd = 0.5f * g_delta[row0 + m];
        float* d = sm + F_AD + m * 272 + r * 17 + c4 * 4;
        d[0] = v.x * sd; d[1] = v.y * sd; d[2] = v.z * sd; d[3] = v.w * sd;
    }
    // stage Bt / Ct / Dt
    {
        int i = tid;
        if (i < 512) {
            sm[F_SBT + i] = g_Bt[row0 * 16 + i];
            sm[F_SCT + i] = g_Ct[row0 * 16 + i];
        }
        if (tid < 32) sm[F_SDT + tid] = g_Dt[row0 + tid];
    }
    // init P = I, q = 0
    if (tid < 272) {
        int r = tid / 17, c = tid % 17;
        sm[F_P0 + tid] = (c < 16 && r == c) ? 1.f : 0.f;
    }
    if (tid < 32) sm[F_QB + tid] = 0.f;
    __syncthreads();

    // phase A: 4 rounds x 8 expm (warps 0-3)
    for (int r = 0; r < 4; r++) {
        if (tid < 128) {
            int gq = tid >> 4, q = tid & 15;
            expm_inplace(sm + F_AD + (r * 8 + gq) * 272, sm + F_SCR + gq * 816, q);
        }
        __syncthreads();
    }

    // phase B: warp 0 does the 32-step (P,q,v,c) scan from smem
    if (tid < 32) {
        const int lane = tid;
        const int i0 = (lane >> 2) * 2, j0 = (lane & 3) * 4;
        float* Pc = sm + F_P0;
        float* Pn = sm + F_P1;
        float* qb = sm + F_QB;
        int qc = 0;
        for (int tt = 0; tt < CS; tt++) {
            const float* Ab = sm + F_AD + tt * 272;
            float c0[4] = {0, 0, 0, 0}, c1[4] = {0, 0, 0, 0};
#pragma unroll
            for (int k = 0; k < 16; k++) {
                float a0 = Ab[i0 * 17 + k], a1 = Ab[(i0 + 1) * 17 + k];
                float b0 = Pc[k * 17 + j0 + 0];
                float b1 = Pc[k * 17 + j0 + 1];
                float b2 = Pc[k * 17 + j0 + 2];
                float b3 = Pc[k * 17 + j0 + 3];
                c0[0] = fmaf(a0, b0, c0[0]); c0[1] = fmaf(a0, b1, c0[1]);
                c0[2] = fmaf(a0, b2, c0[2]); c0[3] = fmaf(a0, b3, c0[3]);
                c1[0] = fmaf(a1, b0, c1[0]); c1[1] = fmaf(a1, b1, c1[1]);
                c1[2] = fmaf(a1, b2, c1[2]); c1[3] = fmaf(a1, b3, c1[3]);
            }
#pragma unroll
            for (int m = 0; m < 4; m++) {
                Pn[i0 * 17 + j0 + m] = c0[m];
                Pn[(i0 + 1) * 17 + j0 + m] = c1[m];
            }
            if (lane < 16) {
                float sn = sm[F_SBT + tt * 16 + lane];
                const float* ar = Ab + lane * 17;
                const float* qo = qb + qc * 16;
#pragma unroll
                for (int k = 0; k < 16; k++) sn = fmaf(ar[k], qo[k], sn);
                qb[(qc ^ 1) * 16 + lane] = sn;
                float p = sm[F_SCT + tt * 16 + lane] * sn;
                p += __shfl_xor_sync(0x0000ffffu, p, 8, 16);
                p += __shfl_xor_sync(0x0000ffffu, p, 4, 16);
                p += __shfl_xor_sync(0x0000ffffu, p, 2, 16);
                p += __shfl_xor_sync(0x0000ffffu, p, 1, 16);
                if (lane == 0) g_C[row0 + tt] = p + sm[F_SDT + tt];
            }
            __syncwarp();
            if (lane >= 16) {
                int j = lane - 16;
                float v = 0.f;
#pragma unroll
                for (int i = 0; i < 16; i++)
                    v = fmaf(sm[F_SCT + tt * 16 + i], Pn[i * 17 + j], v);
                g_V[(row0 + tt) * 16 + j] = v;
            }
            __syncwarp();
            float* tmp = Pc; Pc = Pn; Pn = tmp;
            qc ^= 1;
        }
#pragma unroll
        for (int m = 0; m < 4; m++) {
            g_cP[chunk * 256 + i0 * 16 + j0 + m] = Pc[i0 * 17 + j0 + m];
            g_cP[chunk * 256 + (i0 + 1) * 16 + j0 + m] = Pc[(i0 + 1) * 17 + j0 + m];
        }
        if (lane < 16) g_cq[chunk * 16 + lane] = qb[qc * 16 + lane];
    }
}

// ---------------- scan2: bulk-stage 32 chunks to smem, warp0 scans ----------
__global__ __launch_bounds__(512) void k_scan2()
{
    __shared__ float Ps[32][272];
    __shared__ float qs[32][16];
    const int tid = threadIdx.x;
    const int b = blockIdx.x;
    const int lane = tid & 31;
    float s = 0.f;

    for (int h = 0; h < 2; h++) {
        const int cbase = b * CPB + h * 32;
        for (int i = tid; i < 32 * 256; i += 512) {
            int ch = i >> 8, f = i & 255;
            int r = f >> 4, cc = f & 15;
            Ps[ch][r * 17 + cc] = g_cP[(size_t)(cbase + ch) * 256 + f];
        }
        {
            int ch = tid >> 4;
            if (ch < 32) qs[ch][tid & 15] = g_cq[(cbase + ch) * 16 + (tid & 15)];
        }
        __syncthreads();
        if (tid < 32 && lane < 16) {
            for (int ci = 0; ci < 32; ci++) {
                g_cS[(cbase + ci) * 16 + lane] = s;
                const float* prow = &Ps[ci][lane * 17];
                float a0 = 0.f, a1 = 0.f, a2 = 0.f, a3 = 0.f;
#pragma unroll
                for (int k = 0; k < 4; k++) {
                    a0 = fmaf(prow[k],      __shfl_sync(0xffffu, s, k,      16), a0);
                    a1 = fmaf(prow[k + 4],  __shfl_sync(0xffffu, s, k + 4,  16), a1);
                    a2 = fmaf(prow[k + 8],  __shfl_sync(0xffffu, s, k + 8,  16), a2);
                    a3 = fmaf(prow[k + 12], __shfl_sync(0xffffu, s, k + 12, 16), a3);
                }
                s = ((a0 + a1) + (a2 + a3)) + qs[ci][lane];
            }
        }
        __syncthreads();
    }
}

// ---------------- k_out: y = v . s0 + c ------------------------------------
__global__ __launch_bounds__(256) void k_out(float* __restrict__ y)
{
    const int row = blockIdx.x * 256 + threadIdx.x;
    const int ch = row >> 5;
    const float4* vr = reinterpret_cast<const float4*>(g_V + (size_t)row * 16);
    float4 v0 = vr[0], v1 = vr[1], v2 = vr[2], v3 = vr[3];
    const float4* sr = reinterpret_cast<const float4*>(g_cS + ch * 16);
    float4 s0 = sr[0], s1 = sr[1], s2 = sr[2], s3 = sr[3];
    float a = g_C[row];
    a = fmaf(v0.x, s0.x, a); a = fmaf(v0.y, s0.y, a);
    a = fmaf(v0.z, s0.z, a); a = fmaf(v0.w, s0.w, a);
    a = fmaf(v1.x, s1.x, a); a = fmaf(v1.y, s1.y, a);
    a = fmaf(v1.z, s1.z, a); a = fmaf(v1.w, s1.w, a);
    a = fmaf(v2.x, s2.x, a); a = fmaf(v2.y, s2.y, a);
    a = fmaf(v2.z, s2.z, a); a = fmaf(v2.w, s2.w, a);
    a = fmaf(v3.x, s3.x, a); a = fmaf(v3.y, s3.y, a);
    a = fmaf(v3.z, s3.z, a); a = fmaf(v3.w, s3.w, a);
    y[row] = a;
}

extern "C" void kernel_launch(void* const* d_in, const int* in_sizes, int n_in,
                              void* d_out, int out_size)
{
    const float* u  = (const float*)d_in[0];
    const float* A  = (const float*)d_in[1];
    const float* dp = (const float*)d_in[2];
    const float* Wb = (const float*)d_in[3];
    const float* bb = (const float*)d_in[4];
    const float* Wc = (const float*)d_in[5];
    const float* bc = (const float*)d_in[6];
    const float* Wd = (const float*)d_in[7];
    const float* bd = (const float*)d_in[8];
    float* y = (float*)d_out;

    cudaFuncSetAttribute(k_fused, cudaFuncAttributeMaxDynamicSharedMemorySize,
                         FUSED_SMEM);

    k0_wsplit<<<(40 * 2048) / 256, 256>>>(Wb, Wc, Wd, dp);
    k1_proj<<<ROWS / 64, 128>>>(u, bb, bc, bd);
    k_fused<<<NCHUNK, 512, FUSED_SMEM>>>(A);
    k_scan2<<<BB, 512>>>();
    k_out<<<ROWS / 256, 256>>>(y);
}